// round 2
// baseline (speedup 1.0000x reference)
#include <cuda_runtime.h>
#include <cstdint>
#include <cstddef>

#define DD   256      // embedding dim
#define KK   1024     // num codes
#define NVEC 32768    // 32*32*32 vectors
#define NT   64       // n per block
#define KT   256      // k per tile
#define DT   32       // d per tile
#define ESTR 260      // padded stride of es rows (floats)
#define QSIZE (32*256*32*32)

__device__ float g_xnorm[NVEC];
__device__ float g_enorm[KK];
__device__ int   g_idx[NVEC];

// ---------------------------------------------------------------------------
// prep: xnorm[n] = sum_d x[n,d]^2 (mul-then-add, d ascending, matching
// sum(flat*flat)); enorm[k] = sum_d e[k,d]^2 (tiny, order irrelevant).
// Also zeroes the loss slot.
// ---------------------------------------------------------------------------
__global__ void prep_kernel(const float* __restrict__ latent,
                            const float* __restrict__ codebook,
                            float* __restrict__ d_out, int out_size) {
    int t = blockIdx.x * blockDim.x + threadIdx.x;
    if (t < NVEC) {
        int b = t >> 10, hw = t & 1023;
        const float* p = latent + (size_t)b * DD * 1024 + hw;
        float s = 0.0f;
        #pragma unroll 8
        for (int d = 0; d < DD; d++) {
            float v = p[(size_t)d * 1024];
            s = __fadd_rn(s, __fmul_rn(v, v));   // forbid FMA contraction
        }
        g_xnorm[t] = s;
    } else {
        int u = t - NVEC;                        // warp per k (coalesced)
        int k = u >> 5, lane = u & 31;
        if (k < KK) {
            const float* p = codebook + (size_t)k * DD;
            float s = 0.0f;
            #pragma unroll
            for (int j = 0; j < DD / 32; j++) {
                float v = p[lane + j * 32];
                s = __fadd_rn(s, __fmul_rn(v, v));
            }
            #pragma unroll
            for (int o = 16; o; o >>= 1) s += __shfl_down_sync(0xffffffffu, s, o);
            if (lane == 0) g_enorm[k] = s;
        }
    }
    if (t == 0 && out_size > QSIZE) d_out[QSIZE] = 0.0f;
}

// ---------------------------------------------------------------------------
// argmin: 64 n x 1024 k per block; 8x8 register tile per thread.
// Score = fl(fl(xn+en) - 2*dot), sequential-d fp32 FMA dot, first-index ties.
// ---------------------------------------------------------------------------
__global__ void __launch_bounds__(256)
argmin_kernel(const float* __restrict__ latent,
              const float* __restrict__ codebook) {
    __shared__ float xs[DT * NT];          //  8 KB: x tile transposed [d][n]
    __shared__ float es[DT * ESTR];        // 32.5 KB: e tile transposed [d][k]

    const int tid = threadIdx.x;
    const int tn  = tid & 7;               // 8 n-groups
    const int tk  = tid >> 3;              // 32 k-groups
    const int n0  = blockIdx.x * NT;
    const int b   = n0 >> 10;
    const int hw0 = n0 & 1023;
    const float* lat = latent + (size_t)b * DD * 1024 + hw0;

    float xn[8];
    #pragma unroll
    for (int a = 0; a < 8; a++) xn[a] = g_xnorm[n0 + tn * 8 + a];

    float best[8]; int bidx[8];
    #pragma unroll
    for (int a = 0; a < 8; a++) { best[a] = 3.4e38f; bidx[a] = 0; }

    for (int kt = 0; kt < KK; kt += KT) {
        float acc[8][8];
        #pragma unroll
        for (int a = 0; a < 8; a++)
            #pragma unroll
            for (int c = 0; c < 8; c++) acc[a][c] = 0.0f;

        for (int dt = 0; dt < DD; dt += DT) {
            __syncthreads();                         // prior tile fully read
            // stage x: xs[d][n] = latent[b, dt+d, hw0+n]
            #pragma unroll
            for (int i = 0; i < DT * NT / 256; i++) {
                int f = tid + i * 256;
                xs[f] = lat[(size_t)((dt + (f >> 6))) * 1024 + (f & 63)];
            }
            // stage e transposed: es[dd][k] = codebook[kt+k][dt+dd]
            #pragma unroll
            for (int i = 0; i < 8; i++) {
                int f  = tid + (i << 8);             // 0..2047
                int kk = f >> 3;                     // 0..255
                int dq = f & 7;                      // float4 slot in d
                float4 v = *reinterpret_cast<const float4*>(
                    codebook + (size_t)(kt + kk) * DD + dt + dq * 4);
                es[(dq * 4 + 0) * ESTR + kk] = v.x;
                es[(dq * 4 + 1) * ESTR + kk] = v.y;
                es[(dq * 4 + 2) * ESTR + kk] = v.z;
                es[(dq * 4 + 3) * ESTR + kk] = v.w;
            }
            __syncthreads();
            #pragma unroll 4
            for (int dd = 0; dd < DT; dd++) {
                float4 x0 = *reinterpret_cast<const float4*>(&xs[dd * NT + tn * 8]);
                float4 x1 = *reinterpret_cast<const float4*>(&xs[dd * NT + tn * 8 + 4]);
                float4 e0 = *reinterpret_cast<const float4*>(&es[dd * ESTR + tk * 8]);
                float4 e1 = *reinterpret_cast<const float4*>(&es[dd * ESTR + tk * 8 + 4]);
                float xv[8] = {x0.x, x0.y, x0.z, x0.w, x1.x, x1.y, x1.z, x1.w};
                float ev[8] = {e0.x, e0.y, e0.z, e0.w, e1.x, e1.y, e1.z, e1.w};
                #pragma unroll
                for (int a = 0; a < 8; a++)
                    #pragma unroll
                    for (int c = 0; c < 8; c++)
                        acc[a][c] = fmaf(xv[a], ev[c], acc[a][c]);
            }
        }
        // finalize tile: earliest k wins ties (strict <)
        #pragma unroll
        for (int c = 0; c < 8; c++) {
            int k = kt + tk * 8 + c;
            float en = g_enorm[k];
            #pragma unroll
            for (int a = 0; a < 8; a++) {
                float s = __fsub_rn(__fadd_rn(xn[a], en),
                                    __fmul_rn(2.0f, acc[a][c]));
                if (s < best[a]) { best[a] = s; bidx[a] = k; }
            }
        }
    }

    // cross-thread reduction over 32 k-groups per n (lowest index on ties)
    __syncthreads();
    float* rs = es;                                   // NT*32 floats
    int*   ri = reinterpret_cast<int*>(es + NT * 32); // NT*32 ints
    #pragma unroll
    for (int a = 0; a < 8; a++) {
        int n = tn * 8 + a;
        rs[n * 32 + tk] = best[a];
        ri[n * 32 + tk] = bidx[a];
    }
    __syncthreads();
    if (tid < NT) {
        float bs = rs[tid * 32]; int bi = ri[tid * 32];
        #pragma unroll 4
        for (int t = 1; t < 32; t++) {
            float s = rs[tid * 32 + t]; int ii = ri[tid * 32 + t];
            if (s < bs || (s == bs && ii < bi)) { bs = s; bi = ii; }
        }
        g_idx[n0 + tid] = bi;
    }
}

// ---------------------------------------------------------------------------
// gather: out[b,d,hw] = x + (q - x); loss += 1.25 * sum((q-x)^2) / QSIZE.
// One block per (b,d) row: coalesced x/out; codebook gathers are L2-resident.
// ---------------------------------------------------------------------------
__global__ void gather_kernel(const float* __restrict__ latent,
                              const float* __restrict__ codebook,
                              float* __restrict__ d_out, int out_size) {
    int bd = blockIdx.x;                  // b*256 + d
    int b  = bd >> 8, d = bd & 255;
    const float* xrow = latent + (size_t)bd * 1024;
    float*       orow = d_out + (size_t)bd * 1024;
    const int nbase = b << 10;

    float lsum = 0.0f;
    for (int hw = threadIdx.x; hw < 1024; hw += 256) {
        int   idx  = g_idx[nbase + hw];
        float q    = __ldg(codebook + (size_t)idx * DD + d);
        float x    = xrow[hw];
        float diff = __fsub_rn(q, x);
        orow[hw]   = __fadd_rn(x, diff);  // x + (q - x), as the reference writes it
        lsum      += diff * diff;
    }

    __shared__ float red[256];
    red[threadIdx.x] = lsum;
    __syncthreads();
    #pragma unroll
    for (int s = 128; s > 0; s >>= 1) {
        if (threadIdx.x < s) red[threadIdx.x] += red[threadIdx.x + s];
        __syncthreads();
    }
    if (threadIdx.x == 0 && out_size > QSIZE)
        atomicAdd(d_out + QSIZE, 1.25f * red[0] * (1.0f / (float)QSIZE));
}

extern "C" void kernel_launch(void* const* d_in, const int* in_sizes, int n_in,
                              void* d_out, int out_size) {
    const float* latent   = (const float*)d_in[0];
    const float* codebook = (const float*)d_in[1];
    float* out = (float*)d_out;

    prep_kernel  <<<(NVEC + KK * 32) / 256, 256>>>(latent, codebook, out, out_size);
    argmin_kernel<<<NVEC / NT, 256>>>(latent, codebook);
    gather_kernel<<<32 * 256, 256>>>(latent, codebook, out, out_size);
}

// round 3
// speedup vs baseline: 1.0126x; 1.0126x over previous
#include <cuda_runtime.h>
#include <cstdint>
#include <cstddef>

#define DD   256      // embedding dim
#define KK   1024     // num codes
#define NVEC 32768    // 32*32*32 vectors
#define NT   64       // n per block
#define KT   256      // k per tile
#define DT   32       // d per tile
#define ESTR 260      // padded stride of es rows (floats)
#define QSIZE (32*256*32*32)

__device__ float g_xnorm[NVEC];
__device__ float g_enorm[KK];
__device__ int   g_idx[NVEC];

// ---- packed fp32x2 helpers (sm_103a) --------------------------------------
__device__ __forceinline__ void fma2(unsigned long long& d,
                                     unsigned long long a,
                                     unsigned long long b) {
    asm("fma.rn.f32x2 %0, %1, %2, %0;" : "+l"(d) : "l"(a), "l"(b));
}
__device__ __forceinline__ unsigned long long bcast2(float x) {
    unsigned long long r;
    asm("mov.b64 %0, {%1, %1};" : "=l"(r) : "r"(__float_as_uint(x)));
    return r;
}
__device__ __forceinline__ void unpack2(float& lo, float& hi, unsigned long long v) {
    asm("mov.b64 {%0, %1}, %2;" : "=f"(lo), "=f"(hi) : "l"(v));
}

// ---------------------------------------------------------------------------
// prep: xnorm[n] = sum_d x[n,d]^2 (mul-then-add, d ascending);
//       enorm[k] = sum_d e[k,d]^2. Zeroes the loss slot.
// ---------------------------------------------------------------------------
__global__ void __launch_bounds__(256)
prep_kernel(const float* __restrict__ latent,
            const float* __restrict__ codebook,
            float* __restrict__ d_out, int out_size) {
    int t = blockIdx.x * blockDim.x + threadIdx.x;
    if (t < NVEC) {
        int b = t >> 10, hw = t & 1023;
        const float* p = latent + (size_t)b * DD * 1024 + hw;
        float s = 0.0f;
        #pragma unroll 16
        for (int d = 0; d < DD; d++) {
            float v = __ldg(p + (size_t)d * 1024);
            s = __fadd_rn(s, __fmul_rn(v, v));   // forbid FMA contraction
        }
        g_xnorm[t] = s;
    } else {
        int u = t - NVEC;                        // warp per k (coalesced)
        int k = u >> 5, lane = u & 31;
        if (k < KK) {
            const float* p = codebook + (size_t)k * DD;
            float s = 0.0f;
            #pragma unroll
            for (int j = 0; j < DD / 32; j++) {
                float v = p[lane + j * 32];
                s = __fadd_rn(s, __fmul_rn(v, v));
            }
            #pragma unroll
            for (int o = 16; o; o >>= 1) s += __shfl_down_sync(0xffffffffu, s, o);
            if (lane == 0) g_enorm[k] = s;
        }
    }
    if (t == 0 && out_size > QSIZE) d_out[QSIZE] = 0.0f;
}

// ---------------------------------------------------------------------------
// argmin: 64 n x 1024 k per block; 8x8 register tile per thread, packed as
// 8x4 f32x2 accumulators along k. Score = fl(fl(xn+en) - 2*dot) with a
// sequential-d fp32 FMA dot (f32x2 lanes are exact IEEE fp32 FMAs), ties ->
// lowest k, matching the reference.
// ---------------------------------------------------------------------------
__global__ void __launch_bounds__(256, 2)
argmin_kernel(const float* __restrict__ latent,
              const float* __restrict__ codebook) {
    __shared__ __align__(16) float xs[DT * NT];   //  8 KB x tile [d][n]
    __shared__ __align__(16) float es[DT * ESTR]; // 32.5 KB e tile [d][k]

    const int tid = threadIdx.x;
    const int tn  = tid & 7;               // 8 n-groups
    const int tk  = tid >> 3;              // 32 k-groups
    const int n0  = blockIdx.x * NT;
    const int b   = n0 >> 10;
    const int hw0 = n0 & 1023;
    const float* lat = latent + (size_t)b * DD * 1024 + hw0;

    float xn[8];
    #pragma unroll
    for (int a = 0; a < 8; a++) xn[a] = g_xnorm[n0 + tn * 8 + a];

    float best[8]; int bidx[8];
    #pragma unroll
    for (int a = 0; a < 8; a++) { best[a] = 3.4e38f; bidx[a] = 0; }

    for (int kt = 0; kt < KK; kt += KT) {
        unsigned long long acc[8][4];       // (k even, k odd) pairs
        #pragma unroll
        for (int a = 0; a < 8; a++)
            #pragma unroll
            for (int c = 0; c < 4; c++) acc[a][c] = 0ull;

        for (int dt = 0; dt < DD; dt += DT) {
            __syncthreads();                         // prior tile fully read
            // stage x: xs[d][n] = latent[b, dt+d, hw0+n]
            #pragma unroll
            for (int i = 0; i < DT * NT / 256; i++) {
                int f = tid + i * 256;
                xs[f] = lat[(size_t)(dt + (f >> 6)) * 1024 + (f & 63)];
            }
            // stage e transposed: es[dd][k] = codebook[kt+k][dt+dd]
            #pragma unroll
            for (int i = 0; i < 8; i++) {
                int f  = tid + (i << 8);             // 0..2047
                int kk = f >> 3;                     // 0..255
                int dq = f & 7;                      // float4 slot in d
                float4 v = *reinterpret_cast<const float4*>(
                    codebook + (size_t)(kt + kk) * DD + dt + dq * 4);
                es[(dq * 4 + 0) * ESTR + kk] = v.x;
                es[(dq * 4 + 1) * ESTR + kk] = v.y;
                es[(dq * 4 + 2) * ESTR + kk] = v.z;
                es[(dq * 4 + 3) * ESTR + kk] = v.w;
            }
            __syncthreads();
            #pragma unroll 8
            for (int dd = 0; dd < DT; dd++) {
                float4 x0 = *reinterpret_cast<const float4*>(&xs[dd * NT + tn * 8]);
                float4 x1 = *reinterpret_cast<const float4*>(&xs[dd * NT + tn * 8 + 4]);
                ulonglong2 e0 = *reinterpret_cast<const ulonglong2*>(&es[dd * ESTR + tk * 8]);
                ulonglong2 e1 = *reinterpret_cast<const ulonglong2*>(&es[dd * ESTR + tk * 8 + 4]);
                unsigned long long ee[4] = {e0.x, e0.y, e1.x, e1.y};
                float xv[8] = {x0.x, x0.y, x0.z, x0.w, x1.x, x1.y, x1.z, x1.w};
                #pragma unroll
                for (int a = 0; a < 8; a++) {
                    unsigned long long xa = bcast2(xv[a]);
                    #pragma unroll
                    for (int c = 0; c < 4; c++)
                        fma2(acc[a][c], xa, ee[c]);
                }
            }
        }
        // finalize tile: earliest k wins ties (strict <, ascending k)
        #pragma unroll
        for (int c = 0; c < 4; c++) {
            int k0 = kt + tk * 8 + c * 2;
            float en0 = g_enorm[k0], en1 = g_enorm[k0 + 1];
            #pragma unroll
            for (int a = 0; a < 8; a++) {
                float dlo, dhi;
                unpack2(dlo, dhi, acc[a][c]);
                float s0 = __fsub_rn(__fadd_rn(xn[a], en0), __fmul_rn(2.0f, dlo));
                float s1 = __fsub_rn(__fadd_rn(xn[a], en1), __fmul_rn(2.0f, dhi));
                if (s0 < best[a]) { best[a] = s0; bidx[a] = k0; }
                if (s1 < best[a]) { best[a] = s1; bidx[a] = k0 + 1; }
            }
        }
    }

    // cross-thread reduction over 32 k-groups per n (lowest index on ties)
    __syncthreads();
    float* rs = es;                                   // NT*32 floats
    int*   ri = reinterpret_cast<int*>(es + NT * 32); // NT*32 ints
    #pragma unroll
    for (int a = 0; a < 8; a++) {
        int n = tn * 8 + a;
        rs[n * 32 + tk] = best[a];
        ri[n * 32 + tk] = bidx[a];
    }
    __syncthreads();
    if (tid < NT) {
        float bs = rs[tid * 32]; int bi = ri[tid * 32];
        #pragma unroll 4
        for (int t = 1; t < 32; t++) {
            float s = rs[tid * 32 + t]; int ii = ri[tid * 32 + t];
            if (s < bs || (s == bs && ii < bi)) { bs = s; bi = ii; }
        }
        g_idx[n0 + tid] = bi;
    }
}

// ---------------------------------------------------------------------------
// gather: out[b,d,hw] = x + (q - x); loss += 1.25 * sum((q-x)^2) / QSIZE.
// 4 (b,d) rows per block (2048 blocks -> 2048 same-address atomics),
// float4 x/out; codebook gathers are L2-resident (1 MB).
// ---------------------------------------------------------------------------
__global__ void __launch_bounds__(256)
gather_kernel(const float* __restrict__ latent,
              const float* __restrict__ codebook,
              float* __restrict__ d_out, int out_size) {
    float lsum = 0.0f;
    #pragma unroll
    for (int r = 0; r < 4; r++) {
        int bd = blockIdx.x * 4 + r;          // b*256 + d
        int b  = bd >> 8, d = bd & 255;
        const float4* xrow = reinterpret_cast<const float4*>(latent + (size_t)bd * 1024);
        float4*       orow = reinterpret_cast<float4*>(d_out + (size_t)bd * 1024);
        const int nbase = b << 10;

        int q4 = threadIdx.x;                 // 256 threads x 4 elems = 1024
        int hw = q4 * 4;
        int i0 = g_idx[nbase + hw + 0];
        int i1 = g_idx[nbase + hw + 1];
        int i2 = g_idx[nbase + hw + 2];
        int i3 = g_idx[nbase + hw + 3];
        float4 x = xrow[q4];
        float d0 = __fsub_rn(__ldg(codebook + (size_t)i0 * DD + d), x.x);
        float d1 = __fsub_rn(__ldg(codebook + (size_t)i1 * DD + d), x.y);
        float d2 = __fsub_rn(__ldg(codebook + (size_t)i2 * DD + d), x.z);
        float d3 = __fsub_rn(__ldg(codebook + (size_t)i3 * DD + d), x.w);
        float4 o;
        o.x = __fadd_rn(x.x, d0); o.y = __fadd_rn(x.y, d1);
        o.z = __fadd_rn(x.z, d2); o.w = __fadd_rn(x.w, d3);
        orow[q4] = o;
        lsum += d0 * d0 + d1 * d1 + d2 * d2 + d3 * d3;
    }

    __shared__ float red[256];
    red[threadIdx.x] = lsum;
    __syncthreads();
    #pragma unroll
    for (int s = 128; s > 0; s >>= 1) {
        if (threadIdx.x < s) red[threadIdx.x] += red[threadIdx.x + s];
        __syncthreads();
    }
    if (threadIdx.x == 0 && out_size > QSIZE)
        atomicAdd(d_out + QSIZE, 1.25f * red[0] * (1.0f / (float)QSIZE));
}

extern "C" void kernel_launch(void* const* d_in, const int* in_sizes, int n_in,
                              void* d_out, int out_size) {
    const float* latent   = (const float*)d_in[0];
    const float* codebook = (const float*)d_in[1];
    float* out = (float*)d_out;

    prep_kernel  <<<(NVEC + KK * 32) / 256, 256>>>(latent, codebook, out, out_size);
    argmin_kernel<<<NVEC / NT, 256>>>(latent, codebook);
    gather_kernel<<<32 * 256 / 4, 256>>>(latent, codebook, out, out_size);
}

// round 4
// speedup vs baseline: 2.0247x; 1.9995x over previous
#include <cuda_runtime.h>
#include <cuda_bf16.h>
#include <cstdint>
#include <cstddef>

#define DD    256
#define KK    1024
#define NVEC  32768
#define QSIZE (32*256*32*32)

#define MROWS 128          // rows per GEMM block
#define KCH   128          // codes per k-chunk
#define NCH   (KK / KCH)   // 8 chunks
#define ASTR  264          // padded bf16 row stride (256 + 8)
#define CAP   28           // candidate slots per row
#define EPS   4e-3f        // >= 2 * worst-case bf16 score error (1.8e-3)

__device__ float g_xnorm[NVEC];
__device__ float g_enorm[KK];
__device__ int   g_idx[NVEC];
__device__ __align__(16) float         g_xf[NVEC * DD];   // x transposed [n][d] fp32
__device__ __align__(16) __nv_bfloat16 g_xb[NVEC * DD];   // x transposed [n][d] bf16
__device__ __align__(16) __nv_bfloat16 g_eb[KK * DD];     // codebook bf16 [k][d]

// smem bytes for the GEMM: As + Bs + enorm_s + minval + cnt + cand
#define AS_BYTES (MROWS * ASTR * 2)
#define SMEM_GEMM (AS_BYTES * 2 + 128*4 + 128*4 + 128*4 + 128*CAP*4)

// orderable-uint encoding of float for atomicMin
__device__ __forceinline__ unsigned fenc(float f) {
    unsigned u = __float_as_uint(f);
    return (u & 0x80000000u) ? ~u : (u | 0x80000000u);
}
__device__ __forceinline__ float fdec(unsigned e) {
    return __uint_as_float((e & 0x80000000u) ? (e ^ 0x80000000u) : ~e);
}

// ---------------------------------------------------------------------------
// transpose: latent [b][d][hw] -> g_xf/g_xb [n][d], n = b*1024 + hw
// ---------------------------------------------------------------------------
__global__ void __launch_bounds__(256)
transpose_kernel(const float* __restrict__ latent) {
    __shared__ float ts[64][65];
    int b = blockIdx.x, hw0 = blockIdx.y * 64, d0 = blockIdx.z * 64;
    int hl = threadIdx.x & 63, q = threadIdx.x >> 6;
    #pragma unroll
    for (int j = 0; j < 16; j++) {
        int dl = q + j * 4;
        ts[dl][hl] = latent[((size_t)b * DD + d0 + dl) * 1024 + hw0 + hl];
    }
    __syncthreads();
    #pragma unroll
    for (int j = 0; j < 16; j++) {
        int rl = q + j * 4;                       // hw local
        int c  = hl;                              // d local
        float v = ts[c][rl];
        size_t o = ((size_t)b * 1024 + hw0 + rl) * DD + d0 + c;
        g_xf[o] = v;
        g_xb[o] = __float2bfloat16(v);
    }
}

// ---------------------------------------------------------------------------
// prep: xnorm (sequential-d chain, matches reference sum(flat*flat)),
//       enorm, eb (bf16 codebook), zero loss slot.
// ---------------------------------------------------------------------------
__global__ void __launch_bounds__(256)
prep_kernel(const float* __restrict__ latent,
            const float* __restrict__ codebook,
            float* __restrict__ d_out, int out_size) {
    int t = blockIdx.x * blockDim.x + threadIdx.x;
    if (t < NVEC) {
        int b = t >> 10, hw = t & 1023;
        const float* p = latent + (size_t)b * DD * 1024 + hw;
        float s = 0.0f;
        #pragma unroll 16
        for (int d = 0; d < DD; d++) {
            float v = __ldg(p + (size_t)d * 1024);
            s = __fadd_rn(s, __fmul_rn(v, v));
        }
        g_xnorm[t] = s;
    } else {
        int u = t - NVEC;                         // warp per k
        int k = u >> 5, lane = u & 31;
        if (k < KK) {
            const float* p = codebook + (size_t)k * DD;
            float s = 0.0f;
            #pragma unroll
            for (int j = 0; j < DD / 32; j++) {
                float v = p[lane + j * 32];
                g_eb[(size_t)k * DD + lane + j * 32] = __float2bfloat16(v);
                s = __fadd_rn(s, __fmul_rn(v, v));
            }
            #pragma unroll
            for (int o = 16; o; o >>= 1) s += __shfl_down_sync(0xffffffffu, s, o);
            if (lane == 0) g_enorm[k] = s;
        }
    }
    if (t == 0 && out_size > QSIZE) d_out[QSIZE] = 0.0f;
}

// ---------------------------------------------------------------------------
// GEMM + candidate selection + exact rescore (one block = 128 rows, all 1024 k)
// ---------------------------------------------------------------------------
__device__ __forceinline__ void ldsm4(uint32_t& r0, uint32_t& r1,
                                      uint32_t& r2, uint32_t& r3, uint32_t a) {
    asm volatile("ldmatrix.sync.aligned.m8n8.x4.shared.b16 {%0,%1,%2,%3}, [%4];"
                 : "=r"(r0), "=r"(r1), "=r"(r2), "=r"(r3) : "r"(a));
}
__device__ __forceinline__ void mma_bf16(float& c0, float& c1, float& c2, float& c3,
                                         uint32_t a0, uint32_t a1, uint32_t a2, uint32_t a3,
                                         uint32_t b0, uint32_t b1) {
    asm volatile("mma.sync.aligned.m16n8k16.row.col.f32.bf16.bf16.f32 "
                 "{%0,%1,%2,%3},{%4,%5,%6,%7},{%8,%9},{%0,%1,%2,%3};"
                 : "+f"(c0), "+f"(c1), "+f"(c2), "+f"(c3)
                 : "r"(a0), "r"(a1), "r"(a2), "r"(a3), "r"(b0), "r"(b1));
}

__global__ void __launch_bounds__(256, 1)
gemm_select_kernel(const float* __restrict__ codebook) {
    extern __shared__ char sm[];
    __nv_bfloat16* As = (__nv_bfloat16*)sm;                    // [128][ASTR]
    __nv_bfloat16* Bs = (__nv_bfloat16*)(sm + AS_BYTES);       // [128][ASTR]
    float*    enorm_s = (float*)(sm + 2 * AS_BYTES);
    unsigned* minval  = (unsigned*)(sm + 2 * AS_BYTES + 512);
    int*      cnt     = (int*)(sm + 2 * AS_BYTES + 1024);
    int*      cand    = (int*)(sm + 2 * AS_BYTES + 1536);      // [128][CAP]
    // rescore scratch overlays Bs (free after the k loop)
    float* bS = (float*)Bs;
    int*   bK = (int*)Bs + 256;

    const int tid  = threadIdx.x;
    const int lane = tid & 31, wid = tid >> 5;
    const int wm   = wid >> 2, wn = wid & 3;     // 2 x 4 warp grid
    const int g    = lane >> 2, tq = lane & 3;   // mma group / thread-in-group
    const int n0   = blockIdx.x * MROWS;

    if (tid < 128) { minval[tid] = 0xFFFFFFFFu; cnt[tid] = 0; }

    // Load A block: As[r][d] = g_xb[n0+r][d]   (16 float4 per thread)
    {
        const float4* src = (const float4*)(g_xb + (size_t)n0 * DD);
        #pragma unroll
        for (int j = 0; j < 16; j++) {
            int cc = j * 256 + tid;              // 4096 16B-chunks
            int r = cc >> 5, dc = cc & 31;
            *(float4*)(As + r * ASTR + dc * 8) = src[r * 32 + dc];
        }
    }
    __syncthreads();

    uint32_t asB = (uint32_t)__cvta_generic_to_shared(As);
    uint32_t bsB = (uint32_t)__cvta_generic_to_shared(Bs);
    uint32_t aAddr[4], bAddr[2];
    #pragma unroll
    for (int mi = 0; mi < 4; mi++)
        aAddr[mi] = asB + ((wm * 64 + mi * 16 + (lane & 15)) * ASTR
                           + (lane >> 4) * 8) * 2;
    #pragma unroll
    for (int nb = 0; nb < 2; nb++)
        bAddr[nb] = bsB + ((wn * 32 + nb * 16 + (lane & 7) + ((lane >> 4) & 1) * 8) * ASTR
                           + ((lane >> 3) & 1) * 8) * 2;

    for (int kc = 0; kc < NCH; kc++) {
        const int kb = kc * KCH;
        // stage B chunk + enorm
        {
            const float4* src = (const float4*)(g_eb + (size_t)kb * DD);
            #pragma unroll
            for (int j = 0; j < 16; j++) {
                int cc = j * 256 + tid;
                int r = cc >> 5, dc = cc & 31;
                *(float4*)(Bs + r * ASTR + dc * 8) = src[r * 32 + dc];
            }
            if (tid < 128) enorm_s[tid] = g_enorm[kb + tid];
        }
        __syncthreads();

        float acc[4][4][4];
        #pragma unroll
        for (int mi = 0; mi < 4; mi++)
            #pragma unroll
            for (int ni = 0; ni < 4; ni++)
                #pragma unroll
                for (int jj = 0; jj < 4; jj++) acc[mi][ni][jj] = 0.0f;

        #pragma unroll
        for (int ds = 0; ds < 16; ds++) {
            uint32_t a[4][4], b[4][2];
            #pragma unroll
            for (int mi = 0; mi < 4; mi++)
                ldsm4(a[mi][0], a[mi][1], a[mi][2], a[mi][3], aAddr[mi] + ds * 32);
            #pragma unroll
            for (int nb = 0; nb < 2; nb++)
                ldsm4(b[2*nb][0], b[2*nb][1], b[2*nb+1][0], b[2*nb+1][1],
                      bAddr[nb] + ds * 32);
            #pragma unroll
            for (int mi = 0; mi < 4; mi++)
                #pragma unroll
                for (int ni = 0; ni < 4; ni++)
                    mma_bf16(acc[mi][ni][0], acc[mi][ni][1], acc[mi][ni][2], acc[mi][ni][3],
                             a[mi][0], a[mi][1], a[mi][2], a[mi][3],
                             b[ni][0], b[ni][1]);
        }

        // scores: t = enorm - 2*dot ; per-row atomicMin
        #pragma unroll
        for (int mi = 0; mi < 4; mi++) {
            float m0 = 3.4e38f, m1 = 3.4e38f;
            #pragma unroll
            for (int ni = 0; ni < 4; ni++) {
                int cl = wn * 32 + ni * 8 + 2 * tq;
                float e0 = enorm_s[cl], e1 = enorm_s[cl + 1];
                acc[mi][ni][0] = e0 - 2.0f * acc[mi][ni][0];
                acc[mi][ni][1] = e1 - 2.0f * acc[mi][ni][1];
                acc[mi][ni][2] = e0 - 2.0f * acc[mi][ni][2];
                acc[mi][ni][3] = e1 - 2.0f * acc[mi][ni][3];
                m0 = fminf(m0, fminf(acc[mi][ni][0], acc[mi][ni][1]));
                m1 = fminf(m1, fminf(acc[mi][ni][2], acc[mi][ni][3]));
            }
            m0 = fminf(m0, __shfl_xor_sync(0xffffffffu, m0, 1));
            m0 = fminf(m0, __shfl_xor_sync(0xffffffffu, m0, 2));
            m1 = fminf(m1, __shfl_xor_sync(0xffffffffu, m1, 1));
            m1 = fminf(m1, __shfl_xor_sync(0xffffffffu, m1, 2));
            if (tq == 0) {
                atomicMin(&minval[wm * 64 + mi * 16 + g],     fenc(m0));
                atomicMin(&minval[wm * 64 + mi * 16 + g + 8], fenc(m1));
            }
        }
        __syncthreads();

        // append candidates within eps of running min (conservative-correct)
        #pragma unroll
        for (int mi = 0; mi < 4; mi++) {
            int rl0 = wm * 64 + mi * 16 + g, rl1 = rl0 + 8;
            float t0 = fdec(minval[rl0]) + EPS;
            float t1 = fdec(minval[rl1]) + EPS;
            #pragma unroll
            for (int ni = 0; ni < 4; ni++) {
                int k0 = kb + wn * 32 + ni * 8 + 2 * tq;
                if (acc[mi][ni][0] <= t0) { int p = atomicAdd(&cnt[rl0], 1); if (p < CAP) cand[rl0 * CAP + p] = k0; }
                if (acc[mi][ni][1] <= t0) { int p = atomicAdd(&cnt[rl0], 1); if (p < CAP) cand[rl0 * CAP + p] = k0 + 1; }
                if (acc[mi][ni][2] <= t1) { int p = atomicAdd(&cnt[rl1], 1); if (p < CAP) cand[rl1 * CAP + p] = k0; }
                if (acc[mi][ni][3] <= t1) { int p = atomicAdd(&cnt[rl1], 1); if (p < CAP) cand[rl1 * CAP + p] = k0 + 1; }
            }
        }
        __syncthreads();   // cand/min stable before Bs overwrite next chunk
    }

    // exact rescore of candidates: identical arithmetic to the R2/R3 kernel
    {
        int r = tid & 127, half = tid >> 7;
        int cn = min(cnt[r], CAP);
        float xn = g_xnorm[n0 + r];
        const float4* xp = (const float4*)(g_xf + (size_t)(n0 + r) * DD);
        float bs = 3.4e38f; int bi = 0x7fffffff;
        for (int c = half; c < cn; c += 2) {
            int k = cand[r * CAP + c];
            const float4* ep = (const float4*)(codebook + (size_t)k * DD);
            float a = 0.0f;
            #pragma unroll 8
            for (int i = 0; i < DD / 4; i++) {
                float4 xv = xp[i], ev = ep[i];
                a = fmaf(xv.x, ev.x, a); a = fmaf(xv.y, ev.y, a);
                a = fmaf(xv.z, ev.z, a); a = fmaf(xv.w, ev.w, a);
            }
            float s = __fsub_rn(__fadd_rn(xn, g_enorm[k]), __fmul_rn(2.0f, a));
            if (s < bs || (s == bs && k < bi)) { bs = s; bi = k; }
        }
        bS[half * 128 + r] = bs;
        bK[half * 128 + r] = bi;
    }
    __syncthreads();
    if (tid < 128) {
        float s0 = bS[tid], s1 = bS[128 + tid];
        int   k0 = bK[tid], k1 = bK[128 + tid];
        int win = (s1 < s0 || (s1 == s0 && k1 < k0)) ? k1 : k0;
        g_idx[n0 + tid] = win;
    }
}

// ---------------------------------------------------------------------------
// gather + loss (unchanged from R3)
// ---------------------------------------------------------------------------
__global__ void __launch_bounds__(256)
gather_kernel(const float* __restrict__ latent,
              const float* __restrict__ codebook,
              float* __restrict__ d_out, int out_size) {
    float lsum = 0.0f;
    #pragma unroll
    for (int r = 0; r < 4; r++) {
        int bd = blockIdx.x * 4 + r;
        int b  = bd >> 8, d = bd & 255;
        const float4* xrow = (const float4*)(latent + (size_t)bd * 1024);
        float4*       orow = (float4*)(d_out + (size_t)bd * 1024);
        const int nbase = b << 10;
        int q4 = threadIdx.x;
        int hw = q4 * 4;
        int i0 = g_idx[nbase + hw + 0];
        int i1 = g_idx[nbase + hw + 1];
        int i2 = g_idx[nbase + hw + 2];
        int i3 = g_idx[nbase + hw + 3];
        float4 x = xrow[q4];
        float d0 = __fsub_rn(__ldg(codebook + (size_t)i0 * DD + d), x.x);
        float d1 = __fsub_rn(__ldg(codebook + (size_t)i1 * DD + d), x.y);
        float d2 = __fsub_rn(__ldg(codebook + (size_t)i2 * DD + d), x.z);
        float d3 = __fsub_rn(__ldg(codebook + (size_t)i3 * DD + d), x.w);
        float4 o;
        o.x = __fadd_rn(x.x, d0); o.y = __fadd_rn(x.y, d1);
        o.z = __fadd_rn(x.z, d2); o.w = __fadd_rn(x.w, d3);
        orow[q4] = o;
        lsum += d0 * d0 + d1 * d1 + d2 * d2 + d3 * d3;
    }
    __shared__ float red[256];
    red[threadIdx.x] = lsum;
    __syncthreads();
    #pragma unroll
    for (int s = 128; s > 0; s >>= 1) {
        if (threadIdx.x < s) red[threadIdx.x] += red[threadIdx.x + s];
        __syncthreads();
    }
    if (threadIdx.x == 0 && out_size > QSIZE)
        atomicAdd(d_out + QSIZE, 1.25f * red[0] * (1.0f / (float)QSIZE));
}

extern "C" void kernel_launch(void* const* d_in, const int* in_sizes, int n_in,
                              void* d_out, int out_size) {
    const float* latent   = (const float*)d_in[0];
    const float* codebook = (const float*)d_in[1];
    float* out = (float*)d_out;

    cudaFuncSetAttribute(gemm_select_kernel,
                         cudaFuncAttributeMaxDynamicSharedMemorySize, SMEM_GEMM);

    transpose_kernel<<<dim3(32, 16, 4), 256>>>(latent);
    prep_kernel<<<(NVEC + KK * 32) / 256, 256>>>(latent, codebook, out, out_size);
    gemm_select_kernel<<<NVEC / MROWS, 256, SMEM_GEMM>>>(codebook);
    gather_kernel<<<32 * 256 / 4, 256>>>(latent, codebook, out, out_size);
}

// round 5
// speedup vs baseline: 2.6231x; 1.2955x over previous
#include <cuda_runtime.h>
#include <cuda_bf16.h>
#include <cstdint>
#include <cstddef>

#define DD    256
#define KK    1024
#define NVEC  32768
#define QSIZE (32*256*32*32)

#define MROWS 64           // rows per GEMM block
#define KCH   128          // codes per k-chunk
#define NCH   (KK / KCH)   // 8 chunks
#define ASTR  264          // padded row stride (elements) for xs/As/Bs
#define CAP   28
#define EPS   4e-3f        // validated R4: zero flips

__device__ float g_enorm[KK];
__device__ int   g_idx[NVEC];
__device__ __align__(16) __nv_bfloat16 g_eb[KK * DD];

// smem layout (bytes)
#define XS_B   (MROWS * ASTR * 4)            // 67584 fp32 x tile [r][d]
#define AS_B   (MROWS * ASTR * 2)            // 33792 bf16 A tile
#define BS_B   (KCH * ASTR * 2)              // 67584 bf16 B tile
#define XN_OFF (XS_B + AS_B + BS_B)
#define EN_OFF (XN_OFF + MROWS * 4)
#define MV_OFF (EN_OFF + KCH * 4)
#define CT_OFF (MV_OFF + MROWS * 4)
#define CD_OFF (CT_OFF + MROWS * 4)
#define SMEM_GEMM (CD_OFF + MROWS * CAP * 4)

__device__ __forceinline__ unsigned fenc(float f) {
    unsigned u = __float_as_uint(f);
    return (u & 0x80000000u) ? ~u : (u | 0x80000000u);
}
__device__ __forceinline__ float fdec(unsigned e) {
    return __uint_as_float((e & 0x80000000u) ? (e ^ 0x80000000u) : ~e);
}
__device__ __forceinline__ void cp16(void* dst, const void* src) {
    uint32_t d = (uint32_t)__cvta_generic_to_shared(dst);
    asm volatile("cp.async.cg.shared.global [%0], [%1], 16;" :: "r"(d), "l"(src));
}
__device__ __forceinline__ void ldsm4(uint32_t& r0, uint32_t& r1,
                                      uint32_t& r2, uint32_t& r3, uint32_t a) {
    asm volatile("ldmatrix.sync.aligned.m8n8.x4.shared.b16 {%0,%1,%2,%3}, [%4];"
                 : "=r"(r0), "=r"(r1), "=r"(r2), "=r"(r3) : "r"(a));
}
__device__ __forceinline__ void mma_bf16(float& c0, float& c1, float& c2, float& c3,
                                         uint32_t a0, uint32_t a1, uint32_t a2, uint32_t a3,
                                         uint32_t b0, uint32_t b1) {
    asm volatile("mma.sync.aligned.m16n8k16.row.col.f32.bf16.bf16.f32 "
                 "{%0,%1,%2,%3},{%4,%5,%6,%7},{%8,%9},{%0,%1,%2,%3};"
                 : "+f"(c0), "+f"(c1), "+f"(c2), "+f"(c3)
                 : "r"(a0), "r"(a1), "r"(a2), "r"(a3), "r"(b0), "r"(b1));
}

// ---------------------------------------------------------------------------
// prep: enorm[k] + bf16 codebook; zero loss slot.
// ---------------------------------------------------------------------------
__global__ void __launch_bounds__(256)
prep_kernel(const float* __restrict__ codebook,
            float* __restrict__ d_out, int out_size) {
    int t = blockIdx.x * blockDim.x + threadIdx.x;
    int k = t >> 5, lane = t & 31;
    if (k < KK) {
        const float* p = codebook + (size_t)k * DD;
        float s = 0.0f;
        #pragma unroll
        for (int j = 0; j < DD / 32; j++) {
            float v = p[lane + j * 32];
            g_eb[(size_t)k * DD + lane + j * 32] = __float2bfloat16(v);
            s = __fadd_rn(s, __fmul_rn(v, v));
        }
        #pragma unroll
        for (int o = 16; o; o >>= 1) s += __shfl_down_sync(0xffffffffu, s, o);
        if (lane == 0) g_enorm[k] = s;
    }
    if (t == 0 && out_size > QSIZE) d_out[QSIZE] = 0.0f;
}

// ---------------------------------------------------------------------------
// GEMM + select + exact rescore. Block = 64 hw-contiguous rows, all 1024 k.
// x loaded straight from latent (coalesced), fp32 tile kept in smem.
// ---------------------------------------------------------------------------
__global__ void __launch_bounds__(256, 1)
gemm_select_kernel(const float* __restrict__ latent,
                   const float* __restrict__ codebook) {
    extern __shared__ char sm[];
    float*         xs      = (float*)sm;                        // [64][ASTR] fp32
    __nv_bfloat16* As      = (__nv_bfloat16*)(sm + XS_B);       // [64][ASTR]
    __nv_bfloat16* Bs      = (__nv_bfloat16*)(sm + XS_B + AS_B);// [128][ASTR]
    float*         xn_s    = (float*)(sm + XN_OFF);
    float*         enorm_s = (float*)(sm + EN_OFF);
    unsigned*      minval  = (unsigned*)(sm + MV_OFF);
    int*           cnt     = (int*)(sm + CT_OFF);
    int*           cand    = (int*)(sm + CD_OFF);               // [64][CAP]
    // rescore scratch overlays Bs (dead after k-loop)
    float* bS = (float*)Bs;
    int*   bK = (int*)Bs + 256;

    const int tid  = threadIdx.x;
    const int lane = tid & 31, wid = tid >> 5;
    const int wm   = wid >> 2, wn = wid & 3;     // 2 x 4 warp grid
    const int g    = lane >> 2, tq = lane & 3;
    const int n0   = blockIdx.x * MROWS;
    const int b    = n0 >> 10;
    const int hw0  = n0 & 1023;

    if (tid < MROWS) { minval[tid] = 0xFFFFFFFFu; cnt[tid] = 0; }

    // Load x tile from latent: coalesced over hw. Fill fp32 xs + bf16 As.
    {
        const int hw = tid & 63, dg = tid >> 6;            // dg 0..3
        const float* latb = latent + (size_t)b * DD * 1024 + hw0 + hw;
        #pragma unroll
        for (int j = 0; j < 16; j++) {
            int dbase = j * 16 + dg * 4;
            float v0 = latb[(size_t)(dbase + 0) * 1024];
            float v1 = latb[(size_t)(dbase + 1) * 1024];
            float v2 = latb[(size_t)(dbase + 2) * 1024];
            float v3 = latb[(size_t)(dbase + 3) * 1024];
            float* xr = xs + hw * ASTR + dbase;
            xr[0] = v0; xr[1] = v1; xr[2] = v2; xr[3] = v3;
            uint32_t p0 = ((uint32_t)__bfloat16_as_ushort(__float2bfloat16(v1)) << 16)
                        |  (uint32_t)__bfloat16_as_ushort(__float2bfloat16(v0));
            uint32_t p1 = ((uint32_t)__bfloat16_as_ushort(__float2bfloat16(v3)) << 16)
                        |  (uint32_t)__bfloat16_as_ushort(__float2bfloat16(v2));
            uint32_t* ar = (uint32_t*)(As + hw * ASTR + dbase);
            ar[0] = p0; ar[1] = p1;
        }
    }
    __syncthreads();

    // xnorm: reference-order sequential chain per row (d ascending)
    if (tid < MROWS) {
        const float* xr = xs + tid * ASTR;
        float s = 0.0f;
        #pragma unroll 16
        for (int d = 0; d < DD; d++) {
            float v = xr[d];
            s = __fadd_rn(s, __fmul_rn(v, v));
        }
        xn_s[tid] = s;
    }

    uint32_t asB = (uint32_t)__cvta_generic_to_shared(As);
    uint32_t bsB = (uint32_t)__cvta_generic_to_shared(Bs);
    uint32_t aAddr[2], bAddr[2];
    #pragma unroll
    for (int mi = 0; mi < 2; mi++)
        aAddr[mi] = asB + ((wm * 32 + mi * 16 + (lane & 15)) * ASTR
                           + (lane >> 4) * 8) * 2;
    #pragma unroll
    for (int nb = 0; nb < 2; nb++)
        bAddr[nb] = bsB + ((wn * 32 + nb * 16 + (lane & 7) + ((lane >> 4) & 1) * 8) * ASTR
                           + ((lane >> 3) & 1) * 8) * 2;

    for (int kc = 0; kc < NCH; kc++) {
        const int kb = kc * KCH;
        // stage B chunk via cp.async (16B each, 16 per thread)
        #pragma unroll
        for (int j = 0; j < 16; j++) {
            int cc = j * 256 + tid;
            int r = cc >> 5, dc = cc & 31;
            cp16(Bs + r * ASTR + dc * 8, g_eb + (size_t)(kb + r) * DD + dc * 8);
        }
        asm volatile("cp.async.commit_group;");
        if (tid < KCH) enorm_s[tid] = g_enorm[kb + tid];
        asm volatile("cp.async.wait_group 0;");
        __syncthreads();

        float acc[2][4][4];
        #pragma unroll
        for (int mi = 0; mi < 2; mi++)
            #pragma unroll
            for (int ni = 0; ni < 4; ni++)
                #pragma unroll
                for (int jj = 0; jj < 4; jj++) acc[mi][ni][jj] = 0.0f;

        #pragma unroll
        for (int ds = 0; ds < 16; ds++) {
            uint32_t a[2][4], bfr[4][2];
            #pragma unroll
            for (int mi = 0; mi < 2; mi++)
                ldsm4(a[mi][0], a[mi][1], a[mi][2], a[mi][3], aAddr[mi] + ds * 32);
            #pragma unroll
            for (int nb = 0; nb < 2; nb++)
                ldsm4(bfr[2*nb][0], bfr[2*nb][1], bfr[2*nb+1][0], bfr[2*nb+1][1],
                      bAddr[nb] + ds * 32);
            #pragma unroll
            for (int mi = 0; mi < 2; mi++)
                #pragma unroll
                for (int ni = 0; ni < 4; ni++)
                    mma_bf16(acc[mi][ni][0], acc[mi][ni][1], acc[mi][ni][2], acc[mi][ni][3],
                             a[mi][0], a[mi][1], a[mi][2], a[mi][3],
                             bfr[ni][0], bfr[ni][1]);
        }

        // scores t = enorm - 2*dot ; per-row running min
        #pragma unroll
        for (int mi = 0; mi < 2; mi++) {
            float m0 = 3.4e38f, m1 = 3.4e38f;
            #pragma unroll
            for (int ni = 0; ni < 4; ni++) {
                int cl = wn * 32 + ni * 8 + 2 * tq;
                float e0 = enorm_s[cl], e1 = enorm_s[cl + 1];
                acc[mi][ni][0] = e0 - 2.0f * acc[mi][ni][0];
                acc[mi][ni][1] = e1 - 2.0f * acc[mi][ni][1];
                acc[mi][ni][2] = e0 - 2.0f * acc[mi][ni][2];
                acc[mi][ni][3] = e1 - 2.0f * acc[mi][ni][3];
                m0 = fminf(m0, fminf(acc[mi][ni][0], acc[mi][ni][1]));
                m1 = fminf(m1, fminf(acc[mi][ni][2], acc[mi][ni][3]));
            }
            m0 = fminf(m0, __shfl_xor_sync(0xffffffffu, m0, 1));
            m0 = fminf(m0, __shfl_xor_sync(0xffffffffu, m0, 2));
            m1 = fminf(m1, __shfl_xor_sync(0xffffffffu, m1, 1));
            m1 = fminf(m1, __shfl_xor_sync(0xffffffffu, m1, 2));
            if (tq == 0) {
                atomicMin(&minval[wm * 32 + mi * 16 + g],     fenc(m0));
                atomicMin(&minval[wm * 32 + mi * 16 + g + 8], fenc(m1));
            }
        }
        __syncthreads();

        // append candidates within EPS of running min
        #pragma unroll
        for (int mi = 0; mi < 2; mi++) {
            int rl0 = wm * 32 + mi * 16 + g, rl1 = rl0 + 8;
            float t0 = fdec(minval[rl0]) + EPS;
            float t1 = fdec(minval[rl1]) + EPS;
            #pragma unroll
            for (int ni = 0; ni < 4; ni++) {
                int k0 = kb + wn * 32 + ni * 8 + 2 * tq;
                if (acc[mi][ni][0] <= t0) { int p = atomicAdd(&cnt[rl0], 1); if (p < CAP) cand[rl0 * CAP + p] = k0; }
                if (acc[mi][ni][1] <= t0) { int p = atomicAdd(&cnt[rl0], 1); if (p < CAP) cand[rl0 * CAP + p] = k0 + 1; }
                if (acc[mi][ni][2] <= t1) { int p = atomicAdd(&cnt[rl1], 1); if (p < CAP) cand[rl1 * CAP + p] = k0; }
                if (acc[mi][ni][3] <= t1) { int p = atomicAdd(&cnt[rl1], 1); if (p < CAP) cand[rl1 * CAP + p] = k0 + 1; }
            }
        }
        __syncthreads();
    }

    // exact rescore (identical arithmetic to R2/R4): 4 slots per row
    {
        int r = tid >> 2, c0 = tid & 3;
        int cn = min(cnt[r], CAP);
        float xn = xn_s[r];
        const float4* xp = (const float4*)(xs + r * ASTR);
        float bs = 3.4e38f; int bi = 0x7fffffff;
        for (int c = c0; c < cn; c += 4) {
            int k = cand[r * CAP + c];
            const float4* ep = (const float4*)(codebook + (size_t)k * DD);
            float a = 0.0f;
            #pragma unroll 8
            for (int i = 0; i < DD / 4; i++) {
                float4 xv = xp[i], ev = ep[i];
                a = fmaf(xv.x, ev.x, a); a = fmaf(xv.y, ev.y, a);
                a = fmaf(xv.z, ev.z, a); a = fmaf(xv.w, ev.w, a);
            }
            float s = __fsub_rn(__fadd_rn(xn, g_enorm[k]), __fmul_rn(2.0f, a));
            if (s < bs || (s == bs && k < bi)) { bs = s; bi = k; }
        }
        bS[c0 * 64 + r] = bs;
        bK[c0 * 64 + r] = bi;
    }
    __syncthreads();
    if (tid < MROWS) {
        float bs = bS[tid]; int bi = bK[tid];
        #pragma unroll
        for (int c = 1; c < 4; c++) {
            float s = bS[c * 64 + tid]; int k = bK[c * 64 + tid];
            if (s < bs || (s == bs && k < bi)) { bs = s; bi = k; }
        }
        g_idx[n0 + tid] = bi;
    }
}

// ---------------------------------------------------------------------------
// gather v2: per (b, 64hw, 64d) tile; coalesced codebook row-slices into smem,
// coalesced x/out streaming; loss via block reduce + atomic.
// ---------------------------------------------------------------------------
__global__ void __launch_bounds__(256)
gather_kernel(const float* __restrict__ latent,
              const float* __restrict__ codebook,
              float* __restrict__ d_out, int out_size) {
    __shared__ float qt[64 * 65];
    __shared__ int   idxs[64];
    __shared__ float red[256];

    const int tid = threadIdx.x;
    const int b = blockIdx.x, hw0 = blockIdx.y * 64, d0 = blockIdx.z * 64;

    if (tid < 64) idxs[tid] = g_idx[(b << 10) + hw0 + tid];
    __syncthreads();

    // load codebook[idx[r]][d0 .. d0+63]: 4 threads x 16 floats per row
    {
        int r = tid >> 2, q = tid & 3;
        const float4* cb = (const float4*)(codebook + (size_t)idxs[r] * DD + d0 + q * 16);
        float* dst = qt + r * 65 + q * 16;
        #pragma unroll
        for (int i = 0; i < 4; i++) {
            float4 v = cb[i];
            dst[i * 4 + 0] = v.x; dst[i * 4 + 1] = v.y;
            dst[i * 4 + 2] = v.z; dst[i * 4 + 3] = v.w;
        }
    }
    __syncthreads();

    float lsum = 0.0f;
    const int hwl = tid & 63, dg = tid >> 6;
    #pragma unroll
    for (int j = 0; j < 16; j++) {
        int dl = j * 4 + dg;
        size_t off = ((size_t)b * DD + d0 + dl) * 1024 + hw0 + hwl;
        float x  = latent[off];
        float qv = qt[hwl * 65 + dl];
        float df = __fsub_rn(qv, x);
        d_out[off] = __fadd_rn(x, df);
        lsum += df * df;
    }

    red[tid] = lsum;
    __syncthreads();
    #pragma unroll
    for (int s = 128; s > 0; s >>= 1) {
        if (tid < s) red[tid] += red[tid + s];
        __syncthreads();
    }
    if (tid == 0 && out_size > QSIZE)
        atomicAdd(d_out + QSIZE, 1.25f * red[0] * (1.0f / (float)QSIZE));
}

extern "C" void kernel_launch(void* const* d_in, const int* in_sizes, int n_in,
                              void* d_out, int out_size) {
    const float* latent   = (const float*)d_in[0];
    const float* codebook = (const float*)d_in[1];
    float* out = (float*)d_out;

    cudaFuncSetAttribute(gemm_select_kernel,
                         cudaFuncAttributeMaxDynamicSharedMemorySize, SMEM_GEMM);

    prep_kernel<<<KK * 32 / 256, 256>>>(codebook, out, out_size);
    gemm_select_kernel<<<NVEC / MROWS, 256, SMEM_GEMM>>>(latent, codebook);
    gather_kernel<<<dim3(32, 16, 4), 256>>>(latent, codebook, out, out_size);
}

// round 7
// speedup vs baseline: 2.8873x; 1.1007x over previous
#include <cuda_runtime.h>
#include <cuda_bf16.h>
#include <cstdint>
#include <cstddef>

#define DD    256
#define KK    1024
#define NVEC  32768
#define QSIZE (32*256*32*32)

#define MROWS 128
#define KCH   128
#define NCH   8
#define ASTR  264          // bf16 elements per tile row (pad)
#define XSTR  260          // fp32 rescore tile stride
#define CAP   28
#define EPS   4e-3f        // validated R4/R5: zero flips

__device__ float g_enorm[KK];
__device__ int   g_idx[NVEC];
__device__ __align__(16) __nv_bfloat16 g_eb[KK * DD];

// ---- smem layout (bytes) ----
#define TILE_B   (MROWS * ASTR * 2)          // 67584
#define A_OFF    0
#define B0_OFF   TILE_B
#define B1_OFF   (2 * TILE_B)
#define CTRL     (3 * TILE_B)                // 202752
#define EN_OFF   (CTRL)                      // 128 f32
#define MV_OFF   (EN_OFF + 512)              // 128 u32
#define CT_OFF   (MV_OFF + 512)              // 128 i32
#define XN_OFF   (CT_OFF + 512)              // 128 f32
#define CAND_OFF (XN_OFF + 512)              // 128*CAP i32
#define BS_OFF   (CAND_OFF + 128*CAP*4)      // 256 f32
#define BK_OFF   (BS_OFF + 1024)             // 256 i32
#define SMEM_GEMM (BK_OFF + 1024)            // ~221 KB

__device__ __forceinline__ unsigned fenc(float f) {
    unsigned u = __float_as_uint(f);
    return (u & 0x80000000u) ? ~u : (u | 0x80000000u);
}
__device__ __forceinline__ float fdec(unsigned e) {
    return __uint_as_float((e & 0x80000000u) ? (e ^ 0x80000000u) : ~e);
}
__device__ __forceinline__ void cp16(uint32_t dst, const void* src) {
    asm volatile("cp.async.cg.shared.global [%0], [%1], 16;" :: "r"(dst), "l"(src));
}
__device__ __forceinline__ void ldsm4(uint32_t& r0, uint32_t& r1,
                                      uint32_t& r2, uint32_t& r3, uint32_t a) {
    asm volatile("ldmatrix.sync.aligned.m8n8.x4.shared.b16 {%0,%1,%2,%3}, [%4];"
                 : "=r"(r0), "=r"(r1), "=r"(r2), "=r"(r3) : "r"(a));
}
__device__ __forceinline__ void mma_bf16(float& c0, float& c1, float& c2, float& c3,
                                         uint32_t a0, uint32_t a1, uint32_t a2, uint32_t a3,
                                         uint32_t b0, uint32_t b1) {
    asm volatile("mma.sync.aligned.m16n8k16.row.col.f32.bf16.bf16.f32 "
                 "{%0,%1,%2,%3},{%4,%5,%6,%7},{%8,%9},{%0,%1,%2,%3};"
                 : "+f"(c0), "+f"(c1), "+f"(c2), "+f"(c3)
                 : "r"(a0), "r"(a1), "r"(a2), "r"(a3), "r"(b0), "r"(b1));
}

// ---------------------------------------------------------------------------
// prep: enorm + bf16 codebook; zero loss slot.
// ---------------------------------------------------------------------------
__global__ void __launch_bounds__(256)
prep_kernel(const float* __restrict__ codebook,
            float* __restrict__ d_out, int out_size) {
    int t = blockIdx.x * blockDim.x + threadIdx.x;
    int k = t >> 5, lane = t & 31;
    if (k < KK) {
        const float* p = codebook + (size_t)k * DD;
        float s = 0.0f;
        #pragma unroll
        for (int j = 0; j < DD / 32; j++) {
            float v = p[lane + j * 32];
            g_eb[(size_t)k * DD + lane + j * 32] = __float2bfloat16(v);
            s = __fadd_rn(s, __fmul_rn(v, v));
        }
        #pragma unroll
        for (int o = 16; o; o >>= 1) s += __shfl_down_sync(0xffffffffu, s, o);
        if (lane == 0) g_enorm[k] = s;
    }
    if (t == 0 && out_size > QSIZE) d_out[QSIZE] = 0.0f;
}

// ---------------------------------------------------------------------------
// GEMM (mma.sync, double-buffered B) + select + exact rescore.
// Block = 128 hw-contiguous rows x all 1024 codes.
// ---------------------------------------------------------------------------
__global__ void __launch_bounds__(256, 1)
gemm_select_kernel(const float* __restrict__ latent,
                   const float* __restrict__ codebook) {
    extern __shared__ __align__(1024) char sm[];
    const uint32_t smb = (uint32_t)__cvta_generic_to_shared(sm);
    __nv_bfloat16* As = (__nv_bfloat16*)(sm + A_OFF);
    float*    enorm_s = (float*)(sm + EN_OFF);
    unsigned* minval  = (unsigned*)(sm + MV_OFF);
    int*      cnt     = (int*)(sm + CT_OFF);
    float*    xn_s    = (float*)(sm + XN_OFF);
    int*      cand    = (int*)(sm + CAND_OFF);
    float*    bS      = (float*)(sm + BS_OFF);
    int*      bK      = (int*)(sm + BK_OFF);

    const int tid  = threadIdx.x;
    const int lane = tid & 31, wid = tid >> 5;
    const int wm   = wid >> 2, wn = wid & 3;     // 2 x 4 warp grid
    const int g    = lane >> 2, tq = lane & 3;
    const int n0   = blockIdx.x * MROWS;
    const int b    = n0 >> 10;
    const int hw0  = n0 & 1023;

    if (tid < MROWS) { minval[tid] = 0xFFFFFFFFu; cnt[tid] = 0; }

    // Stage B chunk 0 first so the cp.async runs under the A staging work.
    #pragma unroll
    for (int j = 0; j < 16; j++) {
        int cc = j * 256 + tid;
        int r = cc >> 5, dc = cc & 31;
        cp16(smb + B0_OFF + (uint32_t)(r * ASTR * 2 + dc * 16),
             g_eb + (size_t)r * DD + dc * 8);
    }
    asm volatile("cp.async.commit_group;");

    // Stage A from latent: coalesced over hw; pack bf16 pairs.
    {
        const int hw = tid & 127, dh = tid >> 7;            // dh 0/1
        const float* latb = latent + ((size_t)b * DD + dh * 128) * 1024 + hw0 + hw;
        uint32_t* arow = (uint32_t*)(As + hw * ASTR + dh * 128);
        #pragma unroll
        for (int j = 0; j < 32; j++) {
            float v0 = latb[(size_t)(j * 4 + 0) * 1024];
            float v1 = latb[(size_t)(j * 4 + 1) * 1024];
            float v2 = latb[(size_t)(j * 4 + 2) * 1024];
            float v3 = latb[(size_t)(j * 4 + 3) * 1024];
            uint32_t p0 = ((uint32_t)__bfloat16_as_ushort(__float2bfloat16(v1)) << 16)
                        |  (uint32_t)__bfloat16_as_ushort(__float2bfloat16(v0));
            uint32_t p1 = ((uint32_t)__bfloat16_as_ushort(__float2bfloat16(v3)) << 16)
                        |  (uint32_t)__bfloat16_as_ushort(__float2bfloat16(v2));
            arow[j * 2]     = p0;
            arow[j * 2 + 1] = p1;
        }
    }

    const uint32_t asB = smb + A_OFF;
    uint32_t aAddr[4], bAddr0[2], bAddr1[2];
    #pragma unroll
    for (int mi = 0; mi < 4; mi++)
        aAddr[mi] = asB + ((wm * 64 + mi * 16 + (lane & 15)) * ASTR
                           + (lane >> 4) * 8) * 2;
    #pragma unroll
    for (int nb = 0; nb < 2; nb++) {
        uint32_t rowoff = ((wn * 32 + nb * 16 + (lane & 7) + ((lane >> 4) & 1) * 8) * ASTR
                          + ((lane >> 3) & 1) * 8) * 2;
        bAddr0[nb] = smb + B0_OFF + rowoff;
        bAddr1[nb] = smb + B1_OFF + rowoff;
    }

    for (int c = 0; c < NCH; c++) {
        const int kb = c * KCH;
        if (tid < KCH) enorm_s[tid] = g_enorm[kb + tid];

        if (c < NCH - 1) {   // prefetch next B chunk into the other buffer
            const uint32_t bnxt = (c & 1) ? B0_OFF : B1_OFF;
            #pragma unroll
            for (int j = 0; j < 16; j++) {
                int cc = j * 256 + tid;
                int r = cc >> 5, dc = cc & 31;
                cp16(smb + bnxt + (uint32_t)(r * ASTR * 2 + dc * 16),
                     g_eb + (size_t)(kb + KCH + r) * DD + dc * 8);
            }
            asm volatile("cp.async.commit_group;");
            asm volatile("cp.async.wait_group 1;");    // chunk c's group done
        } else {
            asm volatile("cp.async.wait_group 0;");
        }
        __syncthreads();

        const uint32_t* bAddr = (c & 1) ? bAddr1 : bAddr0;

        float acc[4][4][4];
        #pragma unroll
        for (int mi = 0; mi < 4; mi++)
            #pragma unroll
            for (int ni = 0; ni < 4; ni++)
                #pragma unroll
                for (int jj = 0; jj < 4; jj++) acc[mi][ni][jj] = 0.0f;

        #pragma unroll
        for (int ds = 0; ds < 16; ds++) {
            uint32_t a[4][4], bfr[4][2];
            #pragma unroll
            for (int mi = 0; mi < 4; mi++)
                ldsm4(a[mi][0], a[mi][1], a[mi][2], a[mi][3], aAddr[mi] + ds * 32);
            #pragma unroll
            for (int nb = 0; nb < 2; nb++)
                ldsm4(bfr[2*nb][0], bfr[2*nb][1], bfr[2*nb+1][0], bfr[2*nb+1][1],
                      bAddr[nb] + ds * 32);
            #pragma unroll
            for (int mi = 0; mi < 4; mi++)
                #pragma unroll
                for (int ni = 0; ni < 4; ni++)
                    mma_bf16(acc[mi][ni][0], acc[mi][ni][1], acc[mi][ni][2], acc[mi][ni][3],
                             a[mi][0], a[mi][1], a[mi][2], a[mi][3],
                             bfr[ni][0], bfr[ni][1]);
        }

        // scores t = enorm - 2*dot ; per-row running min (R4-validated)
        #pragma unroll
        for (int mi = 0; mi < 4; mi++) {
            float m0 = 3.4e38f, m1 = 3.4e38f;
            #pragma unroll
            for (int ni = 0; ni < 4; ni++) {
                int cl = wn * 32 + ni * 8 + 2 * tq;
                float e0 = enorm_s[cl], e1 = enorm_s[cl + 1];
                acc[mi][ni][0] = e0 - 2.0f * acc[mi][ni][0];
                acc[mi][ni][1] = e1 - 2.0f * acc[mi][ni][1];
                acc[mi][ni][2] = e0 - 2.0f * acc[mi][ni][2];
                acc[mi][ni][3] = e1 - 2.0f * acc[mi][ni][3];
                m0 = fminf(m0, fminf(acc[mi][ni][0], acc[mi][ni][1]));
                m1 = fminf(m1, fminf(acc[mi][ni][2], acc[mi][ni][3]));
            }
            m0 = fminf(m0, __shfl_xor_sync(0xffffffffu, m0, 1));
            m0 = fminf(m0, __shfl_xor_sync(0xffffffffu, m0, 2));
            m1 = fminf(m1, __shfl_xor_sync(0xffffffffu, m1, 1));
            m1 = fminf(m1, __shfl_xor_sync(0xffffffffu, m1, 2));
            if (tq == 0) {
                atomicMin(&minval[wm * 64 + mi * 16 + g],     fenc(m0));
                atomicMin(&minval[wm * 64 + mi * 16 + g + 8], fenc(m1));
            }
        }
        __syncthreads();

        // append candidates within EPS of running min (R4-validated)
        #pragma unroll
        for (int mi = 0; mi < 4; mi++) {
            int rl0 = wm * 64 + mi * 16 + g, rl1 = rl0 + 8;
            float t0 = fdec(minval[rl0]) + EPS;
            float t1 = fdec(minval[rl1]) + EPS;
            #pragma unroll
            for (int ni = 0; ni < 4; ni++) {
                int k0 = kb + wn * 32 + ni * 8 + 2 * tq;
                if (acc[mi][ni][0] <= t0) { int p = atomicAdd(&cnt[rl0], 1); if (p < CAP) cand[rl0 * CAP + p] = k0; }
                if (acc[mi][ni][1] <= t0) { int p = atomicAdd(&cnt[rl0], 1); if (p < CAP) cand[rl0 * CAP + p] = k0 + 1; }
                if (acc[mi][ni][2] <= t1) { int p = atomicAdd(&cnt[rl1], 1); if (p < CAP) cand[rl1 * CAP + p] = k0; }
                if (acc[mi][ni][3] <= t1) { int p = atomicAdd(&cnt[rl1], 1); if (p < CAP) cand[rl1 * CAP + p] = k0 + 1; }
            }
        }
        __syncthreads();
    }

    // ---- rescore: reload fp32 x over dead A/B tiles; reference-order xnorm ----
    float* xrs = (float*)sm;                          // [128][XSTR] = 130 KB
    {
        const int hw = tid & 127, dh = tid >> 7;
        const float* latb = latent + ((size_t)b * DD + dh * 128) * 1024 + hw0 + hw;
        float* xrow = xrs + hw * XSTR + dh * 128;
        #pragma unroll 8
        for (int j = 0; j < 128; j++)
            xrow[j] = latb[(size_t)j * 1024];
    }
    __syncthreads();
    if (tid < MROWS) {
        const float4* xr = (const float4*)(xrs + tid * XSTR);
        float sum = 0.0f;
        #pragma unroll 8
        for (int i = 0; i < DD / 4; i++) {
            float4 v = xr[i];
            sum = __fadd_rn(sum, __fmul_rn(v.x, v.x));
            sum = __fadd_rn(sum, __fmul_rn(v.y, v.y));
            sum = __fadd_rn(sum, __fmul_rn(v.z, v.z));
            sum = __fadd_rn(sum, __fmul_rn(v.w, v.w));
        }
        xn_s[tid] = sum;
    }
    __syncthreads();
    {
        int r = tid >> 1, half = tid & 1;
        int cn = min(cnt[r], CAP);
        float xn = xn_s[r];
        const float4* xp = (const float4*)(xrs + r * XSTR);
        float bs = 3.4e38f; int bi = 0x7fffffff;
        for (int cc = half; cc < cn; cc += 2) {
            int k = cand[r * CAP + cc];
            const float4* ep = (const float4*)(codebook + (size_t)k * DD);
            float a = 0.0f;
            #pragma unroll 8
            for (int i = 0; i < DD / 4; i++) {
                float4 xv = xp[i], ev = ep[i];
                a = fmaf(xv.x, ev.x, a); a = fmaf(xv.y, ev.y, a);
                a = fmaf(xv.z, ev.z, a); a = fmaf(xv.w, ev.w, a);
            }
            float sc = __fsub_rn(__fadd_rn(xn, g_enorm[k]), __fmul_rn(2.0f, a));
            if (sc < bs || (sc == bs && k < bi)) { bs = sc; bi = k; }
        }
        bS[half * 128 + r] = bs;
        bK[half * 128 + r] = bi;
    }
    __syncthreads();
    if (tid < MROWS) {
        float s0 = bS[tid], s1 = bS[128 + tid];
        int   k0 = bK[tid], k1 = bK[128 + tid];
        g_idx[n0 + tid] = (s1 < s0 || (s1 == s0 && k1 < k0)) ? k1 : k0;
    }
}

// ---------------------------------------------------------------------------
// gather v2 (R5-validated): tiled, coalesced codebook slices via smem.
// ---------------------------------------------------------------------------
__global__ void __launch_bounds__(256)
gather_kernel(const float* __restrict__ latent,
              const float* __restrict__ codebook,
              float* __restrict__ d_out, int out_size) {
    __shared__ float qt[64 * 65];
    __shared__ int   idxs[64];
    __shared__ float red[256];

    const int tid = threadIdx.x;
    const int b = blockIdx.x, hw0 = blockIdx.y * 64, d0 = blockIdx.z * 64;

    if (tid < 64) idxs[tid] = g_idx[(b << 10) + hw0 + tid];
    __syncthreads();
    {
        int r = tid >> 2, q = tid & 3;
        const float4* cb = (const float4*)(codebook + (size_t)idxs[r] * DD + d0 + q * 16);
        float* dst = qt + r * 65 + q * 16;
        #pragma unroll
        for (int i = 0; i < 4; i++) {
            float4 v = cb[i];
            dst[i * 4 + 0] = v.x; dst[i * 4 + 1] = v.y;
            dst[i * 4 + 2] = v.z; dst[i * 4 + 3] = v.w;
        }
    }
    __syncthreads();

    float lsum = 0.0f;
    const int hwl = tid & 63, dg = tid >> 6;
    #pragma unroll
    for (int j = 0; j < 16; j++) {
        int dl = j * 4 + dg;
        size_t off = ((size_t)b * DD + d0 + dl) * 1024 + hw0 + hwl;
        float x  = latent[off];
        float qv = qt[hwl * 65 + dl];
        float df = __fsub_rn(qv, x);
        d_out[off] = __fadd_rn(x, df);
        lsum += df * df;
    }

    red[tid] = lsum;
    __syncthreads();
    #pragma unroll
    for (int s = 128; s > 0; s >>= 1) {
        if (tid < s) red[tid] += red[tid + s];
        __syncthreads();
    }
    if (tid == 0 && out_size > QSIZE)
        atomicAdd(d_out + QSIZE, 1.25f * red[0] * (1.0f / (float)QSIZE));
}

extern "C" void kernel_launch(void* const* d_in, const int* in_sizes, int n_in,
                              void* d_out, int out_size) {
    const float* latent   = (const float*)d_in[0];
    const float* codebook = (const float*)d_in[1];
    float* out = (float*)d_out;

    cudaFuncSetAttribute(gemm_select_kernel,
                         cudaFuncAttributeMaxDynamicSharedMemorySize, SMEM_GEMM);

    prep_kernel<<<KK * 32 / 256, 256>>>(codebook, out, out_size);
    gemm_select_kernel<<<NVEC / MROWS, 256, SMEM_GEMM>>>(latent, codebook);
    gather_kernel<<<dim3(32, 16, 4), 256>>>(latent, codebook, out, out_size);
}